// round 9
// baseline (speedup 1.0000x reference)
#include <cuda_runtime.h>
#include <cuda_fp16.h>
#include <cstdint>

#define Nn 8192
#define IN_F 256
#define OUT_F 128
#define ALPHA 0.2f
#define SPLIT 2
#define JHALF (Nn / SPLIT) /* 4096 */
#define NIT (JHALF / 16)   /* 256 k16 iterations */
#define NBLK (NIT / 8)     /* 32 outer blocks of 128 cols */

// ---------------- scratch (device globals; no allocation allowed) ------------
__device__ float g_f1[Nn];
__device__ float g_f2[Nn];
__device__ float g_f2pmax[256];
__device__ __align__(16) float2 g_tab2[Nn];   // (exp(f2-fm), exp(a*(f2-fm)))
__device__ __align__(16) float2 g_rowc[Nn];   // (cp, cn)
// Wh in fp16, MMA-fragment-major: uint2 index = ((jblk*2 + wn)*8 + nt)*32 + lane
__device__ __align__(16) uint2 g_Bf[(Nn / 16) * 2 * 8 * 32];
// adj bit-packed: uint4 per (row, 128-col block). word v (x..w), bit l = col 128I+4l+v
__device__ __align__(16) uint4 g_adjb[Nn * (Nn / 128)];
__device__ float g_np0[Nn * OUT_F];   // partial numerators
__device__ float g_np1[Nn * OUT_F];
__device__ float g_lp0[Nn];           // partial row sums
__device__ float g_lp1[Nn];

// ---------------- helpers ----------------------------------------------------
__device__ __forceinline__ void mma_f16(float* d, const uint32_t* a, uint32_t b0, uint32_t b1) {
    asm volatile("mma.sync.aligned.m16n8k16.row.col.f32.f16.f16.f32 "
                 "{%0,%1,%2,%3},{%4,%5,%6,%7},{%8,%9},{%0,%1,%2,%3};"
                 : "+f"(d[0]), "+f"(d[1]), "+f"(d[2]), "+f"(d[3])
                 : "r"(a[0]), "r"(a[1]), "r"(a[2]), "r"(a[3]), "r"(b0), "r"(b1));
}

__device__ __forceinline__ uint32_t packh2(float hi, float lo) {
    uint32_t r;
    asm("cvt.rn.f16x2.f32 %0, %1, %2;" : "=r"(r) : "f"(hi), "f"(lo));
    return r;
}

// ---------------------------------------------------------------------------
// Kernel 1: Wh = h@W ; f1/f2, per-block f2 max, fragment-major fp16 Bf,
// and fused adj bit-pack (ballot order matches k_attn's k<->j remap).
// ---------------------------------------------------------------------------
__global__ __launch_bounds__(256) void k_proj(const float* __restrict__ h,
                                              const float* __restrict__ W,
                                              const float* __restrict__ a,
                                              const int* __restrict__ adj) {
    __shared__ float w_s[32 * 128];
    __shared__ float h_s[32 * 33];
    __shared__ float red[32];
    const int tid = threadIdx.x;
    const int i0 = blockIdx.x * 32;
    const int row = tid >> 3;
    const int c8 = tid & 7;
    float4 acc[4];
#pragma unroll
    for (int j4 = 0; j4 < 4; j4++) acc[j4] = make_float4(0.f, 0.f, 0.f, 0.f);

    for (int kc = 0; kc < IN_F; kc += 32) {
        __syncthreads();
        const float4* wsrc = (const float4*)(W + kc * OUT_F);
#pragma unroll
        for (int u = 0; u < 4; u++) ((float4*)w_s)[tid + u * 256] = wsrc[tid + u * 256];
        {
            float4 hv = *(const float4*)(h + (size_t)(i0 + row) * IN_F + kc + c8 * 4);
            h_s[row * 33 + c8 * 4 + 0] = hv.x;
            h_s[row * 33 + c8 * 4 + 1] = hv.y;
            h_s[row * 33 + c8 * 4 + 2] = hv.z;
            h_s[row * 33 + c8 * 4 + 3] = hv.w;
        }
        __syncthreads();
#pragma unroll
        for (int kk = 0; kk < 32; kk++) {
            const float hval = h_s[row * 33 + kk];
            const float4* wr = ((const float4*)w_s) + kk * 32 + c8;
#pragma unroll
            for (int j4 = 0; j4 < 4; j4++) {
                const float4 wv = wr[j4 * 8];
                acc[j4].x = fmaf(hval, wv.x, acc[j4].x);
                acc[j4].y = fmaf(hval, wv.y, acc[j4].y);
                acc[j4].z = fmaf(hval, wv.z, acc[j4].z);
                acc[j4].w = fmaf(hval, wv.w, acc[j4].w);
            }
        }
    }

    // f1 / f2 per row (8 threads per row)
    float s1 = 0.f, s2 = 0.f;
#pragma unroll
    for (int j4 = 0; j4 < 4; j4++) {
        const float4 a1v = *(const float4*)(a + c8 * 4 + j4 * 32);
        const float4 a2v = *(const float4*)(a + OUT_F + c8 * 4 + j4 * 32);
        s1 += acc[j4].x * a1v.x + acc[j4].y * a1v.y + acc[j4].z * a1v.z + acc[j4].w * a1v.w;
        s2 += acc[j4].x * a2v.x + acc[j4].y * a2v.y + acc[j4].z * a2v.z + acc[j4].w * a2v.w;
    }
#pragma unroll
    for (int o = 1; o < 8; o <<= 1) {
        s1 += __shfl_xor_sync(0xFFFFFFFFu, s1, o);
        s2 += __shfl_xor_sync(0xFFFFFFFFu, s2, o);
    }
    if (c8 == 0) { g_f1[i0 + row] = s1; g_f2[i0 + row] = s2; red[row] = s2; }
    __syncthreads();
    if (tid < 32) {
        float m = red[tid];
#pragma unroll
        for (int o = 16; o; o >>= 1) m = fmaxf(m, __shfl_xor_sync(0xFFFFFFFFu, m, o));
        if (tid == 0) g_f2pmax[blockIdx.x] = m;
    }

    // stage Wh into w_s, then fragment-major fp16 write
#pragma unroll
    for (int j4 = 0; j4 < 4; j4++)
        ((float4*)w_s)[row * 32 + c8 + j4 * 8] = acc[j4];
    __syncthreads();

    {
        const int f = tid & 127;
        const int hb = tid >> 7;
        const int wn = f >> 6, nt = (f >> 3) & 7, nq = f & 7;
        uint32_t* bf32 = (uint32_t*)g_Bf;
#pragma unroll
        for (int q = 0; q < 8; q++) {
            const int jj = hb * 16 + 2 * q;
            const float v0 = w_s[jj * 128 + f];
            const float v1 = w_s[(jj + 1) * 128 + f];
            const uint32_t pk = packh2(v1, v0);
            const int jblk = (i0 + jj) >> 4;
            const int cc = (jj >> 2) & 3;
            const int v = jj & 3;
            const int widx = ((((jblk * 2 + wn) * 8 + nt) * 32) + nq * 4 + cc) * 2 + (v >> 1);
            bf32[widx] = pk;
        }
    }

    // ---- fused adj bit-pack: 32 rows x 64 col-blocks, ballot order = (v, lane) ----
    {
        const int w8 = tid >> 5, lane = tid & 31;
        for (int task = w8; task < 32 * 64; task += 8) {
            const int rr = task >> 6, I = task & 63;
            const int4 av = *(const int4*)(adj + (size_t)(i0 + rr) * Nn + I * 128 + lane * 4);
            const uint32_t b0 = __ballot_sync(0xFFFFFFFFu, av.x > 0);
            const uint32_t b1 = __ballot_sync(0xFFFFFFFFu, av.y > 0);
            const uint32_t b2 = __ballot_sync(0xFFFFFFFFu, av.z > 0);
            const uint32_t b3 = __ballot_sync(0xFFFFFFFFu, av.w > 0);
            if (lane == 0)
                g_adjb[(size_t)(i0 + rr) * 64 + I] = make_uint4(b0, b1, b2, b3);
        }
    }
}

// ---------------------------------------------------------------------------
// Kernel 2: finish f2max reduction + build col/row tables. Grid 32 x 256.
// ---------------------------------------------------------------------------
__global__ __launch_bounds__(256) void k_pre() {
    __shared__ float red[256];
    const int t = threadIdx.x;
    red[t] = g_f2pmax[t];
    __syncthreads();
#pragma unroll
    for (int s = 128; s; s >>= 1) {
        if (t < s) red[t] = fmaxf(red[t], red[t + s]);
        __syncthreads();
    }
    const float fm = red[0];
    const int j = blockIdx.x * 256 + t;
    const float d = g_f2[j] - fm;
    g_tab2[j] = make_float2(expf(d), expf(ALPHA * d));
    const float f1 = g_f1[j];
    const float bound = f1 + fm;
    const float m = bound > 0.f ? bound : ALPHA * bound;
    // leaky_relu(s) = max(s, a*s)  =>  p = max(cp*e2p_j, cn*e2n_j)
    g_rowc[j] = make_float2(expf(bound - m), expf(ALPHA * bound - m));
}

// ---------------------------------------------------------------------------
// Kernel 3: fused masked-softmax + fp16 HMMA PV GEMM. Barrier-free main loop.
// adj from bit-packed words (2 wf/iter); p = max(cp*e2p, cn*e2n) masked by bit.
// ---------------------------------------------------------------------------
__global__ __launch_bounds__(512, 1) void k_attn() {
    __shared__ float2 tab_s[JHALF];   // 32 KB

    const int tid = threadIdx.x;
    const int wid = tid >> 5, lane = tid & 31;
    const int wm = wid >> 1, wn = wid & 1;
    const int nq = lane >> 2, c = lane & 3;
    const int rb = blockIdx.x >> 1, half = blockIdx.x & 1;
    const int i0 = rb * 128, jh = half * JHALF;

    // stage the half's exp table into smem (once)
    {
        const float4* src = (const float4*)(g_tab2 + jh);
        float4* dst = (float4*)tab_s;
#pragma unroll
        for (int q = 0; q < 4; q++) dst[tid + q * 512] = src[tid + q * 512];
    }

    const int r0 = i0 + wm * 16 + nq;
    const int r1 = r0 + 8;
    const float2 rc0 = g_rowc[r0];
    const float2 rc1 = g_rowc[r1];
    const float cp0 = rc0.x, cn0 = rc0.y;
    const float cp1 = rc1.x, cn1 = rc1.y;
    const uint4* ab0 = g_adjb + (size_t)r0 * 64 + (jh >> 7);
    const uint4* ab1 = g_adjb + (size_t)r1 * 64 + (jh >> 7);
    const uint2* bfbase = g_Bf + ((size_t)(jh >> 4) * 2 + wn) * 256 + lane;

    float acc[8][4];
#pragma unroll
    for (int nt = 0; nt < 8; nt++)
#pragma unroll
        for (int q = 0; q < 4; q++) acc[nt][q] = 0.f;
    float lsum0 = 0.f, lsum1 = 0.f;

    // B double buffer (copy-free, parity-indexed) + adj word ring
    uint2 bv[2][8];
#pragma unroll
    for (int nt = 0; nt < 8; nt++) bv[0][nt] = bfbase[nt * 32];
    uint4 pw0 = ab0[0], pw1 = ab1[0];

    __syncthreads();   // tab_s ready (only barrier)

    for (int I = 0; I < NBLK; I++) {
        // pre-shift this block's adj words by c (bit (4t) selects col 16t+4c+v)
        const uint32_t s00 = pw0.x >> c, s01 = pw0.y >> c, s02 = pw0.z >> c, s03 = pw0.w >> c;
        const uint32_t s10 = pw1.x >> c, s11 = pw1.y >> c, s12 = pw1.z >> c, s13 = pw1.w >> c;
        if (I + 1 < NBLK) { pw0 = ab0[I + 1]; pw1 = ab1[I + 1]; }

#pragma unroll
        for (int t = 0; t < 8; t++) {
            const int i = I * 8 + t;
            const int jl = 16 * i + 4 * c;
            const uint32_t bit = 1u << (4 * t);

            // prefetch next iteration's B into the other parity slot
            {
                const int inext = (i + 1 < NIT) ? i + 1 : i;
                const uint2* bq = bfbase + (size_t)inext * 512;
#pragma unroll
                for (int nt = 0; nt < 8; nt++) bv[(t + 1) & 1][nt] = bq[nt * 32];
            }

            const float4 tA = *(const float4*)(tab_s + jl);      // cols j, j+1
            const float4 tB = *(const float4*)(tab_s + jl + 2);  // cols j+2, j+3

            float p00 = fmaxf(cp0 * tA.x, cn0 * tA.y);
            float p01 = fmaxf(cp0 * tA.z, cn0 * tA.w);
            float p02 = fmaxf(cp0 * tB.x, cn0 * tB.y);
            float p03 = fmaxf(cp0 * tB.z, cn0 * tB.w);
            float p10 = fmaxf(cp1 * tA.x, cn1 * tA.y);
            float p11 = fmaxf(cp1 * tA.z, cn1 * tA.w);
            float p12 = fmaxf(cp1 * tB.x, cn1 * tB.y);
            float p13 = fmaxf(cp1 * tB.z, cn1 * tB.w);
            p00 = (s00 & bit) ? p00 : 0.f;
            p01 = (s01 & bit) ? p01 : 0.f;
            p02 = (s02 & bit) ? p02 : 0.f;
            p03 = (s03 & bit) ? p03 : 0.f;
            p10 = (s10 & bit) ? p10 : 0.f;
            p11 = (s11 & bit) ? p11 : 0.f;
            p12 = (s12 & bit) ? p12 : 0.f;
            p13 = (s13 & bit) ? p13 : 0.f;
            lsum0 += (p00 + p01) + (p02 + p03);
            lsum1 += (p10 + p11) + (p12 + p13);

            uint32_t Af[4];
            Af[0] = packh2(p01, p00);   // row r0, k 2c/2c+1 (j 4c,4c+1)
            Af[1] = packh2(p11, p10);   // row r1
            Af[2] = packh2(p03, p02);   // row r0, k 2c+8/+9 (j 4c+2,4c+3)
            Af[3] = packh2(p13, p12);   // row r1

#pragma unroll
            for (int nt = 0; nt < 8; nt++)
                mma_f16(acc[nt], Af, bv[t & 1][nt].x, bv[t & 1][nt].y);
        }
    }

    // row-sum reduce across the 4 c-lanes of each quad
    lsum0 += __shfl_xor_sync(0xFFFFFFFFu, lsum0, 1);
    lsum0 += __shfl_xor_sync(0xFFFFFFFFu, lsum0, 2);
    lsum1 += __shfl_xor_sync(0xFFFFFFFFu, lsum1, 1);
    lsum1 += __shfl_xor_sync(0xFFFFFFFFu, lsum1, 2);
    if (wn == 0 && c == 0) {
        float* lp = half ? g_lp1 : g_lp0;
        lp[r0] = lsum0;
        lp[r1] = lsum1;
    }

    // write partial numerators (d0/d1 row r0, d2/d3 row r1, cols 2c,2c+1)
    float* np = half ? g_np1 : g_np0;
#pragma unroll
    for (int nt = 0; nt < 8; nt++) {
        const int col = wn * 64 + nt * 8 + c * 2;
        *(float2*)(np + (size_t)r0 * OUT_F + col) = make_float2(acc[nt][0], acc[nt][1]);
        *(float2*)(np + (size_t)r1 * OUT_F + col) = make_float2(acc[nt][2], acc[nt][3]);
    }
}

// ---------------------------------------------------------------------------
// Kernel 4: combine halves, normalize
// ---------------------------------------------------------------------------
__global__ __launch_bounds__(256) void k_norm(float* __restrict__ out) {
    const int idx = blockIdx.x * 256 + threadIdx.x;  // float4 index
    const int i = idx >> 5;                          // row
    const float inv = 1.f / (g_lp0[i] + g_lp1[i]);
    const float4 x = ((const float4*)g_np0)[idx];
    const float4 y = ((const float4*)g_np1)[idx];
    ((float4*)out)[idx] = make_float4((x.x + y.x) * inv, (x.y + y.y) * inv,
                                      (x.z + y.z) * inv, (x.w + y.w) * inv);
}

// ---------------------------------------------------------------------------
extern "C" void kernel_launch(void* const* d_in, const int* in_sizes, int n_in,
                              void* d_out, int out_size) {
    const float* h   = (const float*)d_in[0];
    const int*   adj = (const int*)d_in[1];
    const float* W   = (const float*)d_in[2];
    const float* a   = (const float*)d_in[3];
    float* out = (float*)d_out;

    k_proj<<<Nn / 32, 256>>>(h, W, a, adj);
    k_pre<<<Nn / 256, 256>>>();
    k_attn<<<(Nn / 128) * SPLIT, 512>>>();
    k_norm<<<Nn * OUT_F / 4 / 256, 256>>>(out);
}

// round 10
// speedup vs baseline: 1.1344x; 1.1344x over previous
#include <cuda_runtime.h>
#include <cuda_fp16.h>
#include <cstdint>

#define Nn 8192
#define IN_F 256
#define OUT_F 128
#define ALPHA 0.2f
#define SPLIT 2
#define JHALF (Nn / SPLIT) /* 4096 */
#define NIT (JHALF / 16)   /* 256 k16 iterations */
#define NBLK (NIT / 8)     /* 32 outer blocks of 128 cols */

// ---------------- scratch (device globals; no allocation allowed) ------------
__device__ float g_f1[Nn];
__device__ float g_f2[Nn];
__device__ float g_f2pmax[256];
__device__ __align__(16) float2 g_tab2[Nn];   // (exp(f2-fm), exp(a*(f2-fm)))
__device__ __align__(16) float2 g_rowc[Nn];   // (cp, cn)
// Wh in fp16, MMA-fragment-major: uint2 index = ((jblk*2 + wn)*8 + nt)*32 + lane
__device__ __align__(16) uint2 g_Bf[(Nn / 16) * 2 * 8 * 32];
// adj bit-packed: uint4 per (row, 128-col block). word v (x..w), bit l = col 128I+4l+v
__device__ __align__(16) uint4 g_adjb[Nn * (Nn / 128)];
__device__ float g_np0[Nn * OUT_F];   // partial numerators
__device__ float g_np1[Nn * OUT_F];
__device__ float g_lp0[Nn];           // partial row sums
__device__ float g_lp1[Nn];

// ---------------- helpers ----------------------------------------------------
__device__ __forceinline__ void mma_f16(float* d, const uint32_t* a, uint32_t b0, uint32_t b1) {
    asm volatile("mma.sync.aligned.m16n8k16.row.col.f32.f16.f16.f32 "
                 "{%0,%1,%2,%3},{%4,%5,%6,%7},{%8,%9},{%0,%1,%2,%3};"
                 : "+f"(d[0]), "+f"(d[1]), "+f"(d[2]), "+f"(d[3])
                 : "r"(a[0]), "r"(a[1]), "r"(a[2]), "r"(a[3]), "r"(b0), "r"(b1));
}

__device__ __forceinline__ uint32_t packh2(float hi, float lo) {
    uint32_t r;
    asm("cvt.rn.f16x2.f32 %0, %1, %2;" : "=r"(r) : "f"(hi), "f"(lo));
    return r;
}

// ---------------------------------------------------------------------------
// Kernel 1: Wh = h@W ; f1/f2, per-block f2 max, fragment-major fp16 Bf,
// fused adj bit-pack with MLP=4 load batching.
// ---------------------------------------------------------------------------
__global__ __launch_bounds__(256) void k_proj(const float* __restrict__ h,
                                              const float* __restrict__ W,
                                              const float* __restrict__ a,
                                              const int* __restrict__ adj) {
    __shared__ float w_s[32 * 128];
    __shared__ float h_s[32 * 33];
    __shared__ float red[32];
    const int tid = threadIdx.x;
    const int i0 = blockIdx.x * 32;
    const int row = tid >> 3;
    const int c8 = tid & 7;
    float4 acc[4];
#pragma unroll
    for (int j4 = 0; j4 < 4; j4++) acc[j4] = make_float4(0.f, 0.f, 0.f, 0.f);

    for (int kc = 0; kc < IN_F; kc += 32) {
        __syncthreads();
        const float4* wsrc = (const float4*)(W + kc * OUT_F);
#pragma unroll
        for (int u = 0; u < 4; u++) ((float4*)w_s)[tid + u * 256] = wsrc[tid + u * 256];
        {
            float4 hv = *(const float4*)(h + (size_t)(i0 + row) * IN_F + kc + c8 * 4);
            h_s[row * 33 + c8 * 4 + 0] = hv.x;
            h_s[row * 33 + c8 * 4 + 1] = hv.y;
            h_s[row * 33 + c8 * 4 + 2] = hv.z;
            h_s[row * 33 + c8 * 4 + 3] = hv.w;
        }
        __syncthreads();
#pragma unroll
        for (int kk = 0; kk < 32; kk++) {
            const float hval = h_s[row * 33 + kk];
            const float4* wr = ((const float4*)w_s) + kk * 32 + c8;
#pragma unroll
            for (int j4 = 0; j4 < 4; j4++) {
                const float4 wv = wr[j4 * 8];
                acc[j4].x = fmaf(hval, wv.x, acc[j4].x);
                acc[j4].y = fmaf(hval, wv.y, acc[j4].y);
                acc[j4].z = fmaf(hval, wv.z, acc[j4].z);
                acc[j4].w = fmaf(hval, wv.w, acc[j4].w);
            }
        }
    }

    // f1 / f2 per row (8 threads per row)
    float s1 = 0.f, s2 = 0.f;
#pragma unroll
    for (int j4 = 0; j4 < 4; j4++) {
        const float4 a1v = *(const float4*)(a + c8 * 4 + j4 * 32);
        const float4 a2v = *(const float4*)(a + OUT_F + c8 * 4 + j4 * 32);
        s1 += acc[j4].x * a1v.x + acc[j4].y * a1v.y + acc[j4].z * a1v.z + acc[j4].w * a1v.w;
        s2 += acc[j4].x * a2v.x + acc[j4].y * a2v.y + acc[j4].z * a2v.z + acc[j4].w * a2v.w;
    }
#pragma unroll
    for (int o = 1; o < 8; o <<= 1) {
        s1 += __shfl_xor_sync(0xFFFFFFFFu, s1, o);
        s2 += __shfl_xor_sync(0xFFFFFFFFu, s2, o);
    }
    if (c8 == 0) { g_f1[i0 + row] = s1; g_f2[i0 + row] = s2; red[row] = s2; }
    __syncthreads();
    if (tid < 32) {
        float m = red[tid];
#pragma unroll
        for (int o = 16; o; o >>= 1) m = fmaxf(m, __shfl_xor_sync(0xFFFFFFFFu, m, o));
        if (tid == 0) g_f2pmax[blockIdx.x] = m;
    }

    // stage Wh into w_s, then fragment-major fp16 write
#pragma unroll
    for (int j4 = 0; j4 < 4; j4++)
        ((float4*)w_s)[row * 32 + c8 + j4 * 8] = acc[j4];
    __syncthreads();

    {
        const int f = tid & 127;
        const int hb = tid >> 7;
        const int wn = f >> 6, nt = (f >> 3) & 7, nq = f & 7;
        uint32_t* bf32 = (uint32_t*)g_Bf;
#pragma unroll
        for (int q = 0; q < 8; q++) {
            const int jj = hb * 16 + 2 * q;
            const float v0 = w_s[jj * 128 + f];
            const float v1 = w_s[(jj + 1) * 128 + f];
            const uint32_t pk = packh2(v1, v0);
            const int jblk = (i0 + jj) >> 4;
            const int cc = (jj >> 2) & 3;
            const int v = jj & 3;
            const int widx = ((((jblk * 2 + wn) * 8 + nt) * 32) + nq * 4 + cc) * 2 + (v >> 1);
            bf32[widx] = pk;
        }
    }

    // ---- fused adj bit-pack, MLP=4: 512 tasks of 4 consecutive 128-col blocks ----
    {
        const int w8 = tid >> 5, lane = tid & 31;
        for (int task = w8; task < 32 * 16; task += 8) {
            const int rr = task >> 4, I4 = task & 15;
            const int* rowp = adj + (size_t)(i0 + rr) * Nn + I4 * 512 + lane * 4;
            const int4 a0 = *(const int4*)(rowp);
            const int4 a1 = *(const int4*)(rowp + 128);
            const int4 a2 = *(const int4*)(rowp + 256);
            const int4 a3 = *(const int4*)(rowp + 384);
            uint4 w0, w1, w2, w3;
            w0.x = __ballot_sync(0xFFFFFFFFu, a0.x > 0);
            w0.y = __ballot_sync(0xFFFFFFFFu, a0.y > 0);
            w0.z = __ballot_sync(0xFFFFFFFFu, a0.z > 0);
            w0.w = __ballot_sync(0xFFFFFFFFu, a0.w > 0);
            w1.x = __ballot_sync(0xFFFFFFFFu, a1.x > 0);
            w1.y = __ballot_sync(0xFFFFFFFFu, a1.y > 0);
            w1.z = __ballot_sync(0xFFFFFFFFu, a1.z > 0);
            w1.w = __ballot_sync(0xFFFFFFFFu, a1.w > 0);
            w2.x = __ballot_sync(0xFFFFFFFFu, a2.x > 0);
            w2.y = __ballot_sync(0xFFFFFFFFu, a2.y > 0);
            w2.z = __ballot_sync(0xFFFFFFFFu, a2.z > 0);
            w2.w = __ballot_sync(0xFFFFFFFFu, a2.w > 0);
            w3.x = __ballot_sync(0xFFFFFFFFu, a3.x > 0);
            w3.y = __ballot_sync(0xFFFFFFFFu, a3.y > 0);
            w3.z = __ballot_sync(0xFFFFFFFFu, a3.z > 0);
            w3.w = __ballot_sync(0xFFFFFFFFu, a3.w > 0);
            if (lane == 0) {
                uint4* dst = g_adjb + (size_t)(i0 + rr) * 64 + I4 * 4;
                dst[0] = w0; dst[1] = w1; dst[2] = w2; dst[3] = w3;
            }
        }
    }
}

// ---------------------------------------------------------------------------
// Kernel 2: finish f2max reduction + build col/row tables. Grid 32 x 256.
// ---------------------------------------------------------------------------
__global__ __launch_bounds__(256) void k_pre() {
    __shared__ float red[256];
    const int t = threadIdx.x;
    red[t] = g_f2pmax[t];
    __syncthreads();
#pragma unroll
    for (int s = 128; s; s >>= 1) {
        if (t < s) red[t] = fmaxf(red[t], red[t + s]);
        __syncthreads();
    }
    const float fm = red[0];
    const int j = blockIdx.x * 256 + t;
    const float d = g_f2[j] - fm;
    g_tab2[j] = make_float2(expf(d), expf(ALPHA * d));
    const float f1 = g_f1[j];
    const float bound = f1 + fm;
    const float m = bound > 0.f ? bound : ALPHA * bound;
    // leaky_relu(s) = max(s, a*s)  =>  p = max(cp*e2p_j, cn*e2n_j)
    g_rowc[j] = make_float2(expf(bound - m), expf(ALPHA * bound - m));
}

// ---------------------------------------------------------------------------
// Kernel 3: fused masked-softmax + fp16 HMMA PV GEMM. Barrier-free main loop.
// adj from bit-packed words (2 wf/iter); p = max(cp*e2p, cn*e2n) masked by bit.
// ---------------------------------------------------------------------------
__global__ __launch_bounds__(512, 1) void k_attn() {
    __shared__ float2 tab_s[JHALF];   // 32 KB

    const int tid = threadIdx.x;
    const int wid = tid >> 5, lane = tid & 31;
    const int wm = wid >> 1, wn = wid & 1;
    const int nq = lane >> 2, c = lane & 3;
    const int rb = blockIdx.x >> 1, half = blockIdx.x & 1;
    const int i0 = rb * 128, jh = half * JHALF;

    // stage the half's exp table into smem (once)
    {
        const float4* src = (const float4*)(g_tab2 + jh);
        float4* dst = (float4*)tab_s;
#pragma unroll
        for (int q = 0; q < 4; q++) dst[tid + q * 512] = src[tid + q * 512];
    }

    const int r0 = i0 + wm * 16 + nq;
    const int r1 = r0 + 8;
    const float2 rc0 = g_rowc[r0];
    const float2 rc1 = g_rowc[r1];
    const float cp0 = rc0.x, cn0 = rc0.y;
    const float cp1 = rc1.x, cn1 = rc1.y;
    const uint4* ab0 = g_adjb + (size_t)r0 * 64 + (jh >> 7);
    const uint4* ab1 = g_adjb + (size_t)r1 * 64 + (jh >> 7);
    const uint2* bfbase = g_Bf + ((size_t)(jh >> 4) * 2 + wn) * 256 + lane;

    float acc[8][4];
#pragma unroll
    for (int nt = 0; nt < 8; nt++)
#pragma unroll
        for (int q = 0; q < 4; q++) acc[nt][q] = 0.f;
    float lsum0 = 0.f, lsum1 = 0.f;

    // B double buffer (copy-free, parity-indexed) + adj word ring
    uint2 bv[2][8];
#pragma unroll
    for (int nt = 0; nt < 8; nt++) bv[0][nt] = bfbase[nt * 32];
    uint4 pw0 = ab0[0], pw1 = ab1[0];

    __syncthreads();   // tab_s ready (only barrier)

    for (int I = 0; I < NBLK; I++) {
        // pre-shift this block's adj words by c (bit (4t) selects col 16t+4c+v)
        const uint32_t s00 = pw0.x >> c, s01 = pw0.y >> c, s02 = pw0.z >> c, s03 = pw0.w >> c;
        const uint32_t s10 = pw1.x >> c, s11 = pw1.y >> c, s12 = pw1.z >> c, s13 = pw1.w >> c;
        if (I + 1 < NBLK) { pw0 = ab0[I + 1]; pw1 = ab1[I + 1]; }

#pragma unroll
        for (int t = 0; t < 8; t++) {
            const int i = I * 8 + t;
            const int jl = 16 * i + 4 * c;
            const uint32_t bit = 1u << (4 * t);

            // prefetch next iteration's B into the other parity slot
            {
                const int inext = (i + 1 < NIT) ? i + 1 : i;
                const uint2* bq = bfbase + (size_t)inext * 512;
#pragma unroll
                for (int nt = 0; nt < 8; nt++) bv[(t + 1) & 1][nt] = bq[nt * 32];
            }

            const float4 tA = *(const float4*)(tab_s + jl);      // cols j, j+1
            const float4 tB = *(const float4*)(tab_s + jl + 2);  // cols j+2, j+3

            float p00 = fmaxf(cp0 * tA.x, cn0 * tA.y);
            float p01 = fmaxf(cp0 * tA.z, cn0 * tA.w);
            float p02 = fmaxf(cp0 * tB.x, cn0 * tB.y);
            float p03 = fmaxf(cp0 * tB.z, cn0 * tB.w);
            float p10 = fmaxf(cp1 * tA.x, cn1 * tA.y);
            float p11 = fmaxf(cp1 * tA.z, cn1 * tA.w);
            float p12 = fmaxf(cp1 * tB.x, cn1 * tB.y);
            float p13 = fmaxf(cp1 * tB.z, cn1 * tB.w);
            p00 = (s00 & bit) ? p00 : 0.f;
            p01 = (s01 & bit) ? p01 : 0.f;
            p02 = (s02 & bit) ? p02 : 0.f;
            p03 = (s03 & bit) ? p03 : 0.f;
            p10 = (s10 & bit) ? p10 : 0.f;
            p11 = (s11 & bit) ? p11 : 0.f;
            p12 = (s12 & bit) ? p12 : 0.f;
            p13 = (s13 & bit) ? p13 : 0.f;
            lsum0 += (p00 + p01) + (p02 + p03);
            lsum1 += (p10 + p11) + (p12 + p13);

            uint32_t Af[4];
            Af[0] = packh2(p01, p00);   // row r0, k 2c/2c+1 (j 4c,4c+1)
            Af[1] = packh2(p11, p10);   // row r1
            Af[2] = packh2(p03, p02);   // row r0, k 2c+8/+9 (j 4c+2,4c+3)
            Af[3] = packh2(p13, p12);   // row r1

#pragma unroll
            for (int nt = 0; nt < 8; nt++)
                mma_f16(acc[nt], Af, bv[t & 1][nt].x, bv[t & 1][nt].y);
        }
    }

    // row-sum reduce across the 4 c-lanes of each quad
    lsum0 += __shfl_xor_sync(0xFFFFFFFFu, lsum0, 1);
    lsum0 += __shfl_xor_sync(0xFFFFFFFFu, lsum0, 2);
    lsum1 += __shfl_xor_sync(0xFFFFFFFFu, lsum1, 1);
    lsum1 += __shfl_xor_sync(0xFFFFFFFFu, lsum1, 2);
    if (wn == 0 && c == 0) {
        float* lp = half ? g_lp1 : g_lp0;
        lp[r0] = lsum0;
        lp[r1] = lsum1;
    }

    // write partial numerators (d0/d1 row r0, d2/d3 row r1, cols 2c,2c+1)
    float* np = half ? g_np1 : g_np0;
#pragma unroll
    for (int nt = 0; nt < 8; nt++) {
        const int col = wn * 64 + nt * 8 + c * 2;
        *(float2*)(np + (size_t)r0 * OUT_F + col) = make_float2(acc[nt][0], acc[nt][1]);
        *(float2*)(np + (size_t)r1 * OUT_F + col) = make_float2(acc[nt][2], acc[nt][3]);
    }
}

// ---------------------------------------------------------------------------
// Kernel 4: combine halves, normalize
// ---------------------------------------------------------------------------
__global__ __launch_bounds__(256) void k_norm(float* __restrict__ out) {
    const int idx = blockIdx.x * 256 + threadIdx.x;  // float4 index
    const int i = idx >> 5;                          // row
    const float inv = 1.f / (g_lp0[i] + g_lp1[i]);
    const float4 x = ((const float4*)g_np0)[idx];
    const float4 y = ((const float4*)g_np1)[idx];
    ((float4*)out)[idx] = make_float4((x.x + y.x) * inv, (x.y + y.y) * inv,
                                      (x.z + y.z) * inv, (x.w + y.w) * inv);
}

// ---------------------------------------------------------------------------
extern "C" void kernel_launch(void* const* d_in, const int* in_sizes, int n_in,
                              void* d_out, int out_size) {
    const float* h   = (const float*)d_in[0];
    const int*   adj = (const int*)d_in[1];
    const float* W   = (const float*)d_in[2];
    const float* a   = (const float*)d_in[3];
    float* out = (float*)d_out;

    k_proj<<<Nn / 32, 256>>>(h, W, a, adj);
    k_pre<<<Nn / 256, 256>>>();
    k_attn<<<(Nn / 128) * SPLIT, 512>>>();
    k_norm<<<Nn * OUT_F / 4 / 256, 256>>>(out);
}

// round 11
// speedup vs baseline: 1.4441x; 1.2729x over previous
#include <cuda_runtime.h>
#include <cuda_fp16.h>
#include <cstdint>

#define Nn 8192
#define IN_F 256
#define OUT_F 128
#define ALPHA 0.2f
#define SPLIT 2
#define JHALF (Nn / SPLIT) /* 4096 */
#define NIT (JHALF / 16)   /* 256 k16 iterations */
#define NBLK (NIT / 8)     /* 32 outer blocks of 128 cols */

#define ADJ_STRIDE 132     /* words per packed row (128 + 4 pad) */
#define SMEM_TAB   32768
#define SMEM_ATTN  (SMEM_TAB + 128 * ADJ_STRIDE * 4)  /* 32KB tab + 67.6KB bits */

// ---------------- scratch (device globals; no allocation allowed) ------------
__device__ float g_f1[Nn];
__device__ float g_f2[Nn];
__device__ float g_f2pmax[256];
__device__ __align__(16) float2 g_tab2[Nn];   // (exp(f2-fm), exp(a*(f2-fm)))
__device__ __align__(16) float2 g_rowc[Nn];   // (cp, cn)
// Wh in fp16, MMA-fragment-major: uint2 index = ((jblk*2 + wn)*8 + nt)*32 + lane
__device__ __align__(16) uint2 g_Bf[(Nn / 16) * 2 * 8 * 32];
__device__ float g_np0[Nn * OUT_F];   // partial numerators
__device__ float g_np1[Nn * OUT_F];
__device__ float g_lp0[Nn];           // partial row sums
__device__ float g_lp1[Nn];

// ---------------- helpers ----------------------------------------------------
__device__ __forceinline__ void mma_f16(float* d, const uint32_t* a, uint32_t b0, uint32_t b1) {
    asm volatile("mma.sync.aligned.m16n8k16.row.col.f32.f16.f16.f32 "
                 "{%0,%1,%2,%3},{%4,%5,%6,%7},{%8,%9},{%0,%1,%2,%3};"
                 : "+f"(d[0]), "+f"(d[1]), "+f"(d[2]), "+f"(d[3])
                 : "r"(a[0]), "r"(a[1]), "r"(a[2]), "r"(a[3]), "r"(b0), "r"(b1));
}

__device__ __forceinline__ uint32_t packh2(float hi, float lo) {
    uint32_t r;
    asm("cvt.rn.f16x2.f32 %0, %1, %2;" : "=r"(r) : "f"(hi), "f"(lo));
    return r;
}

// ---------------------------------------------------------------------------
// Kernel 1: Wh = h@W ; f1/f2, per-block f2 max, fragment-major fp16 Bf. (=R8)
// ---------------------------------------------------------------------------
__global__ __launch_bounds__(256) void k_proj(const float* __restrict__ h,
                                              const float* __restrict__ W,
                                              const float* __restrict__ a) {
    __shared__ float w_s[32 * 128];
    __shared__ float h_s[32 * 33];
    __shared__ float red[32];
    const int tid = threadIdx.x;
    const int i0 = blockIdx.x * 32;
    const int row = tid >> 3;
    const int c8 = tid & 7;
    float4 acc[4];
#pragma unroll
    for (int j4 = 0; j4 < 4; j4++) acc[j4] = make_float4(0.f, 0.f, 0.f, 0.f);

    for (int kc = 0; kc < IN_F; kc += 32) {
        __syncthreads();
        const float4* wsrc = (const float4*)(W + kc * OUT_F);
#pragma unroll
        for (int u = 0; u < 4; u++) ((float4*)w_s)[tid + u * 256] = wsrc[tid + u * 256];
        {
            float4 hv = *(const float4*)(h + (size_t)(i0 + row) * IN_F + kc + c8 * 4);
            h_s[row * 33 + c8 * 4 + 0] = hv.x;
            h_s[row * 33 + c8 * 4 + 1] = hv.y;
            h_s[row * 33 + c8 * 4 + 2] = hv.z;
            h_s[row * 33 + c8 * 4 + 3] = hv.w;
        }
        __syncthreads();
#pragma unroll
        for (int kk = 0; kk < 32; kk++) {
            const float hval = h_s[row * 33 + kk];
            const float4* wr = ((const float4*)w_s) + kk * 32 + c8;
#pragma unroll
            for (int j4 = 0; j4 < 4; j4++) {
                const float4 wv = wr[j4 * 8];
                acc[j4].x = fmaf(hval, wv.x, acc[j4].x);
                acc[j4].y = fmaf(hval, wv.y, acc[j4].y);
                acc[j4].z = fmaf(hval, wv.z, acc[j4].z);
                acc[j4].w = fmaf(hval, wv.w, acc[j4].w);
            }
        }
    }

    float s1 = 0.f, s2 = 0.f;
#pragma unroll
    for (int j4 = 0; j4 < 4; j4++) {
        const float4 a1v = *(const float4*)(a + c8 * 4 + j4 * 32);
        const float4 a2v = *(const float4*)(a + OUT_F + c8 * 4 + j4 * 32);
        s1 += acc[j4].x * a1v.x + acc[j4].y * a1v.y + acc[j4].z * a1v.z + acc[j4].w * a1v.w;
        s2 += acc[j4].x * a2v.x + acc[j4].y * a2v.y + acc[j4].z * a2v.z + acc[j4].w * a2v.w;
    }
#pragma unroll
    for (int o = 1; o < 8; o <<= 1) {
        s1 += __shfl_xor_sync(0xFFFFFFFFu, s1, o);
        s2 += __shfl_xor_sync(0xFFFFFFFFu, s2, o);
    }
    if (c8 == 0) { g_f1[i0 + row] = s1; g_f2[i0 + row] = s2; red[row] = s2; }
    __syncthreads();
    if (tid < 32) {
        float m = red[tid];
#pragma unroll
        for (int o = 16; o; o >>= 1) m = fmaxf(m, __shfl_xor_sync(0xFFFFFFFFu, m, o));
        if (tid == 0) g_f2pmax[blockIdx.x] = m;
    }

#pragma unroll
    for (int j4 = 0; j4 < 4; j4++)
        ((float4*)w_s)[row * 32 + c8 + j4 * 8] = acc[j4];
    __syncthreads();

    const int f = tid & 127;
    const int hb = tid >> 7;
    const int wn = f >> 6, nt = (f >> 3) & 7, nq = f & 7;
    uint32_t* bf32 = (uint32_t*)g_Bf;
#pragma unroll
    for (int q = 0; q < 8; q++) {
        const int jj = hb * 16 + 2 * q;
        const float v0 = w_s[jj * 128 + f];
        const float v1 = w_s[(jj + 1) * 128 + f];
        const uint32_t pk = packh2(v1, v0);
        const int jblk = (i0 + jj) >> 4;
        const int cc = (jj >> 2) & 3;
        const int v = jj & 3;
        const int widx = ((((jblk * 2 + wn) * 8 + nt) * 32) + nq * 4 + cc) * 2 + (v >> 1);
        bf32[widx] = pk;
    }
}

// ---------------------------------------------------------------------------
// Kernel 2: finish f2max reduction + build col/row tables. Grid 32 x 256.
// ---------------------------------------------------------------------------
__global__ __launch_bounds__(256) void k_pre() {
    __shared__ float red[256];
    const int t = threadIdx.x;
    red[t] = g_f2pmax[t];
    __syncthreads();
#pragma unroll
    for (int s = 128; s; s >>= 1) {
        if (t < s) red[t] = fmaxf(red[t], red[t + s]);
        __syncthreads();
    }
    const float fm = red[0];
    const int j = blockIdx.x * 256 + t;
    const float d = g_f2[j] - fm;
    g_tab2[j] = make_float2(expf(d), expf(ALPHA * d));
    const float f1 = g_f1[j];
    const float bound = f1 + fm;
    const float m = bound > 0.f ? bound : ALPHA * bound;
    // leaky_relu(s) = max(s, a*s)  =>  p = max(cp*e2p_j, cn*e2n_j)
    g_rowc[j] = make_float2(expf(bound - m), expf(ALPHA * bound - m));
}

// ---------------------------------------------------------------------------
// Kernel 3: fused masked-softmax + fp16 HMMA PV GEMM.
// Preamble: CTA packs its 128x4096 adj region into smem bits (coalesced,
// read-once). Main loop: masks via conflict-free LDS (0.25 wf/iter).
// ---------------------------------------------------------------------------
__global__ __launch_bounds__(512, 1) void k_attn(const int* __restrict__ adj) {
    extern __shared__ char smem_dyn[];
    float2* tab_s = (float2*)smem_dyn;                          // 32 KB
    uint32_t* adjb_s = (uint32_t*)(smem_dyn + SMEM_TAB);        // 128 x 132 words

    const int tid = threadIdx.x;
    const int wid = tid >> 5, lane = tid & 31;
    const int wm = wid >> 1, wn = wid & 1;
    const int nq = lane >> 2, c = lane & 3;
    const int rb = blockIdx.x >> 1, half = blockIdx.x & 1;
    const int i0 = rb * 128, jh = half * JHALF;

    // ---- stage exp table ----
    {
        const float4* src = (const float4*)(g_tab2 + jh);
        float4* dst = (float4*)tab_s;
#pragma unroll
        for (int q = 0; q < 4; q++) dst[tid + q * 512] = src[tid + q * 512];
    }

    // ---- pack adj bits: warp w handles rows w*8..w*8+7 (coalesced, MLP=4) ----
    {
        const int wrow = wid * 8;
#pragma unroll 1
        for (int rr = 0; rr < 8; rr++) {
            const int* src = adj + (size_t)(i0 + wrow + rr) * Nn + jh + lane * 4;
            uint32_t* drow = adjb_s + (wrow + rr) * ADJ_STRIDE;
#pragma unroll 1
            for (int I4 = 0; I4 < 8; I4++) {
                const int4 a0 = *(const int4*)(src + I4 * 512);
                const int4 a1 = *(const int4*)(src + I4 * 512 + 128);
                const int4 a2 = *(const int4*)(src + I4 * 512 + 256);
                const int4 a3 = *(const int4*)(src + I4 * 512 + 384);
                uint4 w0, w1, w2, w3;
                w0.x = __ballot_sync(0xFFFFFFFFu, a0.x > 0);
                w0.y = __ballot_sync(0xFFFFFFFFu, a0.y > 0);
                w0.z = __ballot_sync(0xFFFFFFFFu, a0.z > 0);
                w0.w = __ballot_sync(0xFFFFFFFFu, a0.w > 0);
                w1.x = __ballot_sync(0xFFFFFFFFu, a1.x > 0);
                w1.y = __ballot_sync(0xFFFFFFFFu, a1.y > 0);
                w1.z = __ballot_sync(0xFFFFFFFFu, a1.z > 0);
                w1.w = __ballot_sync(0xFFFFFFFFu, a1.w > 0);
                w2.x = __ballot_sync(0xFFFFFFFFu, a2.x > 0);
                w2.y = __ballot_sync(0xFFFFFFFFu, a2.y > 0);
                w2.z = __ballot_sync(0xFFFFFFFFu, a2.z > 0);
                w2.w = __ballot_sync(0xFFFFFFFFu, a2.w > 0);
                w3.x = __ballot_sync(0xFFFFFFFFu, a3.x > 0);
                w3.y = __ballot_sync(0xFFFFFFFFu, a3.y > 0);
                w3.z = __ballot_sync(0xFFFFFFFFu, a3.z > 0);
                w3.w = __ballot_sync(0xFFFFFFFFu, a3.w > 0);
                if (lane == 0) {
                    *(uint4*)(drow + I4 * 16 + 0)  = w0;
                    *(uint4*)(drow + I4 * 16 + 4)  = w1;
                    *(uint4*)(drow + I4 * 16 + 8)  = w2;
                    *(uint4*)(drow + I4 * 16 + 12) = w3;
                }
            }
        }
    }

    const int r0 = i0 + wm * 16 + nq;
    const int r1 = r0 + 8;
    const float2 rc0 = g_rowc[r0];
    const float2 rc1 = g_rowc[r1];
    const float cp0 = rc0.x, cn0 = rc0.y;
    const float cp1 = rc1.x, cn1 = rc1.y;
    const uint32_t* mrow0 = adjb_s + (wm * 16 + nq) * ADJ_STRIDE;
    const uint32_t* mrow1 = mrow0 + 8 * ADJ_STRIDE;
    const uint2* bfbase = g_Bf + ((size_t)(jh >> 4) * 2 + wn) * 256 + lane;

    float acc[8][4];
#pragma unroll
    for (int nt = 0; nt < 8; nt++)
#pragma unroll
        for (int q = 0; q < 4; q++) acc[nt][q] = 0.f;
    float lsum0 = 0.f, lsum1 = 0.f;

    // B double buffer (copy-free, parity-indexed)
    uint2 bv[2][8];
#pragma unroll
    for (int nt = 0; nt < 8; nt++) bv[0][nt] = bfbase[nt * 32];

    __syncthreads();   // pack + tab ready (only barrier)

    for (int I = 0; I < NBLK; I++) {
        const uint4 pw0 = *(const uint4*)(mrow0 + I * 4);
        const uint4 pw1 = *(const uint4*)(mrow1 + I * 4);
        const uint32_t s00 = pw0.x >> c, s01 = pw0.y >> c, s02 = pw0.z >> c, s03 = pw0.w >> c;
        const uint32_t s10 = pw1.x >> c, s11 = pw1.y >> c, s12 = pw1.z >> c, s13 = pw1.w >> c;

#pragma unroll
        for (int t = 0; t < 8; t++) {
            const int i = I * 8 + t;
            const int jl = 16 * i + 4 * c;
            const uint32_t bit = 1u << (4 * t);

            // prefetch next iteration's B into the other parity slot
            {
                const int inext = (i + 1 < NIT) ? i + 1 : i;
                const uint2* bq = bfbase + (size_t)inext * 512;
#pragma unroll
                for (int nt = 0; nt < 8; nt++) bv[(t + 1) & 1][nt] = bq[nt * 32];
            }

            const float4 tA = *(const float4*)(tab_s + jl);      // cols j, j+1
            const float4 tB = *(const float4*)(tab_s + jl + 2);  // cols j+2, j+3

            float p00 = fmaxf(cp0 * tA.x, cn0 * tA.y);
            float p01 = fmaxf(cp0 * tA.z, cn0 * tA.w);
            float p02 = fmaxf(cp0 * tB.x, cn0 * tB.y);
            float p03 = fmaxf(cp0 * tB.z, cn0 * tB.w);
            float p10 = fmaxf(cp1 * tA.x, cn1 * tA.y);
            float p11 = fmaxf(cp1 * tA.z, cn1 * tA.w);
            float p12 = fmaxf(cp1 * tB.x, cn1 * tB.y);
            float p13 = fmaxf(cp1 * tB.z, cn1 * tB.w);
            p00 = (s00 & bit) ? p00 : 0.f;
            p01 = (s01 & bit) ? p01 : 0.f;
            p02 = (s02 & bit) ? p02 : 0.f;
            p03 = (s03 & bit) ? p03 : 0.f;
            p10 = (s10 & bit) ? p10 : 0.f;
            p11 = (s11 & bit) ? p11 : 0.f;
            p12 = (s12 & bit) ? p12 : 0.f;
            p13 = (s13 & bit) ? p13 : 0.f;
            lsum0 += (p00 + p01) + (p02 + p03);
            lsum1 += (p10 + p11) + (p12 + p13);

            uint32_t Af[4];
            Af[0] = packh2(p01, p00);   // row r0, k 2c/2c+1 (j 4c,4c+1)
            Af[1] = packh2(p11, p10);   // row r1
            Af[2] = packh2(p03, p02);   // row r0, k 2c+8/+9 (j 4c+2,4c+3)
            Af[3] = packh2(p13, p12);   // row r1

#pragma unroll
            for (int nt = 0; nt < 8; nt++)
                mma_f16(acc[nt], Af, bv[t & 1][nt].x, bv[t & 1][nt].y);
        }
    }

    // row-sum reduce across the 4 c-lanes of each quad
    lsum0 += __shfl_xor_sync(0xFFFFFFFFu, lsum0, 1);
    lsum0 += __shfl_xor_sync(0xFFFFFFFFu, lsum0, 2);
    lsum1 += __shfl_xor_sync(0xFFFFFFFFu, lsum1, 1);
    lsum1 += __shfl_xor_sync(0xFFFFFFFFu, lsum1, 2);
    if (wn == 0 && c == 0) {
        float* lp = half ? g_lp1 : g_lp0;
        lp[r0] = lsum0;
        lp[r1] = lsum1;
    }

    // write partial numerators (d0/d1 row r0, d2/d3 row r1, cols 2c,2c+1)
    float* np = half ? g_np1 : g_np0;
#pragma unroll
    for (int nt = 0; nt < 8; nt++) {
        const int col = wn * 64 + nt * 8 + c * 2;
        *(float2*)(np + (size_t)r0 * OUT_F + col) = make_float2(acc[nt][0], acc[nt][1]);
        *(float2*)(np + (size_t)r1 * OUT_F + col) = make_float2(acc[nt][2], acc[nt][3]);
    }
}

// ---------------------------------------------------------------------------
// Kernel 4: combine halves, normalize
// ---------------------------------------------------------------------------
__global__ __launch_bounds__(256) void k_norm(float* __restrict__ out) {
    const int idx = blockIdx.x * 256 + threadIdx.x;  // float4 index
    const int i = idx >> 5;                          // row
    const float inv = 1.f / (g_lp0[i] + g_lp1[i]);
    const float4 x = ((const float4*)g_np0)[idx];
    const float4 y = ((const float4*)g_np1)[idx];
    ((float4*)out)[idx] = make_float4((x.x + y.x) * inv, (x.y + y.y) * inv,
                                      (x.z + y.z) * inv, (x.w + y.w) * inv);
}

// ---------------------------------------------------------------------------
extern "C" void kernel_launch(void* const* d_in, const int* in_sizes, int n_in,
                              void* d_out, int out_size) {
    const float* h   = (const float*)d_in[0];
    const int*   adj = (const int*)d_in[1];
    const float* W   = (const float*)d_in[2];
    const float* a   = (const float*)d_in[3];
    float* out = (float*)d_out;

    static int smem_set = 0;
    if (!smem_set) {
        cudaFuncSetAttribute(k_attn, cudaFuncAttributeMaxDynamicSharedMemorySize, SMEM_ATTN);
        smem_set = 1;
    }

    k_proj<<<Nn / 32, 256>>>(h, W, a);
    k_pre<<<Nn / 256, 256>>>();
    k_attn<<<(Nn / 128) * SPLIT, 512, SMEM_ATTN>>>(adj);
    k_norm<<<Nn * OUT_F / 4 / 256, 256>>>(out);
}

// round 12
// speedup vs baseline: 1.9769x; 1.3690x over previous
#include <cuda_runtime.h>
#include <cuda_fp16.h>
#include <cstdint>

#define Nn 8192
#define IN_F 256
#define OUT_F 128
#define ALPHA 0.2f
#define SPLIT 2
#define JHALF (Nn / SPLIT) /* 4096 */
#define NIT (JHALF / 16)   /* 256 k16 iterations */

// ---------------- scratch (device globals; no allocation allowed) ------------
__device__ float g_f1[Nn];
__device__ float g_f2[Nn];
__device__ float g_f2pmax[256];
__device__ __align__(16) float2 g_tab2[Nn];   // (exp(f2-fm), exp(a*(f2-fm)))
__device__ __align__(16) float2 g_rowc[Nn];   // (cp, cn)
// Wh in fp16, MMA-fragment-major, uint4-paired n-tiles:
//   uint4 index = (((jblk*2 + wn)*4 + ntp)*32 + lane)
//   .x/.y = b0/b1 of nt=2*ntp ; .z/.w = b0/b1 of nt=2*ntp+1
__device__ __align__(16) uint4 g_Bf[(Nn / 16) * 2 * 4 * 32];
__device__ float g_np0[Nn * OUT_F];   // partial numerators
__device__ float g_np1[Nn * OUT_F];
__device__ float g_lp0[Nn];           // partial row sums
__device__ float g_lp1[Nn];

// ---------------- helpers ----------------------------------------------------
__device__ __forceinline__ void mma_f16(float* d, const uint32_t* a, uint32_t b0, uint32_t b1) {
    asm volatile("mma.sync.aligned.m16n8k16.row.col.f32.f16.f16.f32 "
                 "{%0,%1,%2,%3},{%4,%5,%6,%7},{%8,%9},{%0,%1,%2,%3};"
                 : "+f"(d[0]), "+f"(d[1]), "+f"(d[2]), "+f"(d[3])
                 : "r"(a[0]), "r"(a[1]), "r"(a[2]), "r"(a[3]), "r"(b0), "r"(b1));
}

__device__ __forceinline__ uint32_t packh2(float hi, float lo) {
    uint32_t r;
    asm("cvt.rn.f16x2.f32 %0, %1, %2;" : "=r"(r) : "f"(hi), "f"(lo));
    return r;
}

// ---------------------------------------------------------------------------
// Kernel 1: Wh = h@W ; f1/f2, per-block f2 max, fragment-major fp16 Bf.
// ---------------------------------------------------------------------------
__global__ __launch_bounds__(256) void k_proj(const float* __restrict__ h,
                                              const float* __restrict__ W,
                                              const float* __restrict__ a) {
    __shared__ float w_s[32 * 128];
    __shared__ float h_s[32 * 33];
    __shared__ float red[32];
    const int tid = threadIdx.x;
    const int i0 = blockIdx.x * 32;
    const int row = tid >> 3;
    const int c8 = tid & 7;
    float4 acc[4];
#pragma unroll
    for (int j4 = 0; j4 < 4; j4++) acc[j4] = make_float4(0.f, 0.f, 0.f, 0.f);

    for (int kc = 0; kc < IN_F; kc += 32) {
        __syncthreads();
        const float4* wsrc = (const float4*)(W + kc * OUT_F);
#pragma unroll
        for (int u = 0; u < 4; u++) ((float4*)w_s)[tid + u * 256] = wsrc[tid + u * 256];
        {
            float4 hv = *(const float4*)(h + (size_t)(i0 + row) * IN_F + kc + c8 * 4);
            h_s[row * 33 + c8 * 4 + 0] = hv.x;
            h_s[row * 33 + c8 * 4 + 1] = hv.y;
            h_s[row * 33 + c8 * 4 + 2] = hv.z;
            h_s[row * 33 + c8 * 4 + 3] = hv.w;
        }
        __syncthreads();
#pragma unroll
        for (int kk = 0; kk < 32; kk++) {
            const float hval = h_s[row * 33 + kk];
            const float4* wr = ((const float4*)w_s) + kk * 32 + c8;
#pragma unroll
            for (int j4 = 0; j4 < 4; j4++) {
                const float4 wv = wr[j4 * 8];
                acc[j4].x = fmaf(hval, wv.x, acc[j4].x);
                acc[j4].y = fmaf(hval, wv.y, acc[j4].y);
                acc[j4].z = fmaf(hval, wv.z, acc[j4].z);
                acc[j4].w = fmaf(hval, wv.w, acc[j4].w);
            }
        }
    }

    float s1 = 0.f, s2 = 0.f;
#pragma unroll
    for (int j4 = 0; j4 < 4; j4++) {
        const float4 a1v = *(const float4*)(a + c8 * 4 + j4 * 32);
        const float4 a2v = *(const float4*)(a + OUT_F + c8 * 4 + j4 * 32);
        s1 += acc[j4].x * a1v.x + acc[j4].y * a1v.y + acc[j4].z * a1v.z + acc[j4].w * a1v.w;
        s2 += acc[j4].x * a2v.x + acc[j4].y * a2v.y + acc[j4].z * a2v.z + acc[j4].w * a2v.w;
    }
#pragma unroll
    for (int o = 1; o < 8; o <<= 1) {
        s1 += __shfl_xor_sync(0xFFFFFFFFu, s1, o);
        s2 += __shfl_xor_sync(0xFFFFFFFFu, s2, o);
    }
    if (c8 == 0) { g_f1[i0 + row] = s1; g_f2[i0 + row] = s2; red[row] = s2; }
    __syncthreads();
    if (tid < 32) {
        float m = red[tid];
#pragma unroll
        for (int o = 16; o; o >>= 1) m = fmaxf(m, __shfl_xor_sync(0xFFFFFFFFu, m, o));
        if (tid == 0) g_f2pmax[blockIdx.x] = m;
    }

    // stage Wh into w_s, then fragment-major fp16 write (uint4-paired layout)
#pragma unroll
    for (int j4 = 0; j4 < 4; j4++)
        ((float4*)w_s)[row * 32 + c8 + j4 * 8] = acc[j4];
    __syncthreads();

    const int f = tid & 127;
    const int hb = tid >> 7;
    const int wn = f >> 6, nt = (f >> 3) & 7, nq = f & 7;
    uint32_t* bf32 = (uint32_t*)g_Bf;
#pragma unroll
    for (int q = 0; q < 8; q++) {
        const int jj = hb * 16 + 2 * q;
        const float v0 = w_s[jj * 128 + f];
        const float v1 = w_s[(jj + 1) * 128 + f];
        const uint32_t pk = packh2(v1, v0);
        const int jblk = (i0 + jj) >> 4;
        const int cc = (jj >> 2) & 3;
        const int v = jj & 3;
        const int widx = ((((jblk * 2 + wn) * 4 + (nt >> 1)) * 32) + nq * 4 + cc) * 4
                         + (nt & 1) * 2 + (v >> 1);
        bf32[widx] = pk;
    }
}

// ---------------------------------------------------------------------------
// Kernel 2: finish f2max reduction + build col/row tables. Grid 32 x 256.
// ---------------------------------------------------------------------------
__global__ __launch_bounds__(256) void k_pre() {
    __shared__ float red[256];
    const int t = threadIdx.x;
    red[t] = g_f2pmax[t];
    __syncthreads();
#pragma unroll
    for (int s = 128; s; s >>= 1) {
        if (t < s) red[t] = fmaxf(red[t], red[t + s]);
        __syncthreads();
    }
    const float fm = red[0];
    const int j = blockIdx.x * 256 + t;
    const float d = g_f2[j] - fm;
    g_tab2[j] = make_float2(expf(d), expf(ALPHA * d));
    const float f1 = g_f1[j];
    const float bound = f1 + fm;
    const float m = bound > 0.f ? bound : ALPHA * bound;
    // leaky_relu(s) = max(s, a*s)  =>  p = max(cp*e2p_j, cn*e2n_j)
    g_rowc[j] = make_float2(expf(bound - m), expf(ALPHA * bound - m));
}

// ---------------------------------------------------------------------------
// Kernel 3: fused masked-softmax + fp16 HMMA PV GEMM. Barrier-free main loop.
// adj raw int4 streaming (R8-style); B as 4 coalesced LDG.128 per iter.
// ---------------------------------------------------------------------------
__global__ __launch_bounds__(512, 1) void k_attn(const int* __restrict__ adj) {
    __shared__ float2 tab_s[JHALF];   // 32 KB

    const int tid = threadIdx.x;
    const int wid = tid >> 5, lane = tid & 31;
    const int wm = wid >> 1, wn = wid & 1;
    const int nq = lane >> 2, c = lane & 3;
    const int rb = blockIdx.x >> 1, half = blockIdx.x & 1;
    const int i0 = rb * 128, jh = half * JHALF;

    // stage the half's exp table into smem (once)
    {
        const float4* src = (const float4*)(g_tab2 + jh);
        float4* dst = (float4*)tab_s;
#pragma unroll
        for (int q = 0; q < 4; q++) dst[tid + q * 512] = src[tid + q * 512];
    }

    const int r0 = i0 + wm * 16 + nq;
    const int r1 = r0 + 8;
    const float2 rc0 = g_rowc[r0];
    const float2 rc1 = g_rowc[r1];
    const float cp0 = rc0.x, cn0 = rc0.y;
    const float cp1 = rc1.x, cn1 = rc1.y;
    const int4* arow0 = (const int4*)(adj + (size_t)r0 * Nn);
    const int4* arow1 = (const int4*)(adj + (size_t)r1 * Nn);
    const int cibase = (jh >> 2) + c;
    const uint4* bfbase = g_Bf + ((size_t)(jh >> 4) * 2 + wn) * 128 + lane;

    float acc[8][4];
#pragma unroll
    for (int nt = 0; nt < 8; nt++)
#pragma unroll
        for (int q = 0; q < 4; q++) acc[nt][q] = 0.f;
    float lsum0 = 0.f, lsum1 = 0.f;

    // adj prefetch ring, distance 2
    int4 pa0[2], pa1[2];
    pa0[0] = arow0[cibase];     pa1[0] = arow1[cibase];
    pa0[1] = arow0[cibase + 4]; pa1[1] = arow1[cibase + 4];

    // B double buffer (copy-free, parity-indexed): 4 uint4 per iter
    uint4 bv[2][4];
#pragma unroll
    for (int ntp = 0; ntp < 4; ntp++) bv[0][ntp] = bfbase[ntp * 32];

    __syncthreads();   // tab_s ready (only barrier)

#pragma unroll 2
    for (int i = 0; i < NIT; i++) {
        const int jl = 16 * i + 4 * c;
        const int4 A0 = pa0[i & 1];
        const int4 A1 = pa1[i & 1];
        if (i + 2 < NIT) {
            pa0[i & 1] = arow0[cibase + 4 * (i + 2)];
            pa1[i & 1] = arow1[cibase + 4 * (i + 2)];
        }

        // prefetch next iteration's B into the other parity slot
        {
            const int inext = (i + 1 < NIT) ? i + 1 : i;
            const uint4* bq = bfbase + (size_t)inext * 256;
#pragma unroll
            for (int ntp = 0; ntp < 4; ntp++) bv[(i + 1) & 1][ntp] = bq[ntp * 32];
        }

        const float4 tA = *(const float4*)(tab_s + jl);      // cols j, j+1
        const float4 tB = *(const float4*)(tab_s + jl + 2);  // cols j+2, j+3

        float p00 = fmaxf(cp0 * tA.x, cn0 * tA.y);
        float p01 = fmaxf(cp0 * tA.z, cn0 * tA.w);
        float p02 = fmaxf(cp0 * tB.x, cn0 * tB.y);
        float p03 = fmaxf(cp0 * tB.z, cn0 * tB.w);
        float p10 = fmaxf(cp1 * tA.x, cn1 * tA.y);
        float p11 = fmaxf(cp1 * tA.z, cn1 * tA.w);
        float p12 = fmaxf(cp1 * tB.x, cn1 * tB.y);
        float p13 = fmaxf(cp1 * tB.z, cn1 * tB.w);
        p00 = (A0.x > 0) ? p00 : 0.f;
        p01 = (A0.y > 0) ? p01 : 0.f;
        p02 = (A0.z > 0) ? p02 : 0.f;
        p03 = (A0.w > 0) ? p03 : 0.f;
        p10 = (A1.x > 0) ? p10 : 0.f;
        p11 = (A1.y > 0) ? p11 : 0.f;
        p12 = (A1.z > 0) ? p12 : 0.f;
        p13 = (A1.w > 0) ? p13 : 0.f;
        lsum0 += (p00 + p01) + (p02 + p03);
        lsum1 += (p10 + p11) + (p12 + p13);

        uint32_t Af[4];
        Af[0] = packh2(p01, p00);   // row r0, k 2c/2c+1 (j 4c,4c+1)
        Af[1] = packh2(p11, p10);   // row r1
        Af[2] = packh2(p03, p02);   // row r0, k 2c+8/+9 (j 4c+2,4c+3)
        Af[3] = packh2(p13, p12);   // row r1

        const uint4* bcur = bv[i & 1];
#pragma unroll
        for (int ntp = 0; ntp < 4; ntp++) {
            mma_f16(acc[2 * ntp + 0], Af, bcur[ntp].x, bcur[ntp].y);
            mma_f16(acc[2 * ntp + 1], Af, bcur[ntp].z, bcur[ntp].w);
        }
    }

    // row-sum reduce across the 4 c-lanes of each quad
    lsum0 += __shfl_xor_sync(0xFFFFFFFFu, lsum0, 1);
    lsum0 += __shfl_xor_sync(0xFFFFFFFFu, lsum0, 2);
    lsum1 += __shfl_xor_sync(0xFFFFFFFFu, lsum1, 1);
    lsum1 += __shfl_xor_sync(0xFFFFFFFFu, lsum1, 2);
    if (wn == 0 && c == 0) {
        float* lp = half ? g_lp1 : g_lp0;
        lp[r0] = lsum0;
        lp[r1] = lsum1;
    }

    // write partial numerators (d0/d1 row r0, d2/d3 row r1, cols 2c,2c+1)
    float* np = half ? g_np1 : g_np0;
#pragma unroll
    for (int nt = 0; nt < 8; nt++) {
        const int col = wn * 64 + nt * 8 + c * 2;
        *(float2*)(np + (size_t)r0 * OUT_F + col) = make_float2(acc[nt][0], acc[nt][1]);
        *(float2*)(np + (size_t)r1 * OUT_F + col) = make_float2(acc[nt][2], acc[nt][3]);
    }
}

// ---------------------------------------------------------------------------
// Kernel 4: combine halves, normalize
// ---------------------------------------------------------------------------
__global__ __launch_bounds__(256) void k_norm(float* __restrict__ out) {
    const int idx = blockIdx.x * 256 + threadIdx.x;  // float4 index
    const int i = idx >> 5;                          // row
    const float inv = 1.f / (g_lp0[i] + g_lp1[i]);
    const float4 x = ((const float4*)g_np0)[idx];
    const float4 y = ((const float4*)g_np1)[idx];
    ((float4*)out)[idx] = make_float4((x.x + y.x) * inv, (x.y + y.y) * inv,
                                      (x.z + y.z) * inv, (x.w + y.w) * inv);
}

// ---------------------------------------------------------------------------
extern "C" void kernel_launch(void* const* d_in, const int* in_sizes, int n_in,
                              void* d_out, int out_size) {
    const float* h   = (const float*)d_in[0];
    const int*   adj = (const int*)d_in[1];
    const float* W   = (const float*)d_in[2];
    const float* a   = (const float*)d_in[3];
    float* out = (float*)d_out;

    k_proj<<<Nn / 32, 256>>>(h, W, a);
    k_pre<<<Nn / 256, 256>>>();
    k_attn<<<(Nn / 128) * SPLIT, 512>>>(adj);
    k_norm<<<Nn * OUT_F / 4 / 256, 256>>>(out);
}